// round 14
// baseline (speedup 1.0000x reference)
#include <cuda_runtime.h>
#include <cuda_bf16.h>
#include <math.h>

// ---------------- problem constants ----------------
#define BATCH 512
#define TIN   512
#define CCH   6
#define HID   12
#define NLAY  120
#define T1    508
#define T2    504
#define RD    16
#define NTH3  256
#define NOUT  (BATCH*NLAY*HID)

typedef unsigned long long u64;
typedef unsigned int u32;

// ---------------- smem layout for k_lstm3 ----------------
#define SA_HI 0
#define SA_LO 40960
#define SG    81920
#define SW_HI 180416
#define SW_LO 183488
#define LSTM3_SMEM 186560

// ---------------- device scratch ----------------
__device__ double g_s1[CCH], g_q1[CCH], g_s2[CCH], g_q2[CCH];
__device__ float  g_bn1[2*CCH];
__device__ float  g_bn2[2*CCH];
__device__ float  g_buf1[BATCH*CCH*T1];
__device__ float  g_buf2[BATCH*CCH*T2];
__device__ float  g_seq [BATCH*T2*HID];
__device__ float  g_hid [BATCH*NLAY*HID];
__device__ float  g_ring[(size_t)NLAY*RD*BATCH*HID];
__device__ int    g_flag[NLAY];
__device__ int    g_done[NLAY+1];

// ---------------- helpers ----------------
__device__ __forceinline__ float tanh_t(float x) {
    float y;
    asm("tanh.approx.f32 %0, %1;" : "=f"(y) : "f"(x));
    return y;
}
__device__ __forceinline__ float sigm_pre(float hx) {
    return fmaf(0.5f, tanh_t(hx), 0.5f);
}
__device__ __forceinline__ u32 pkbf2(float lo_val, float hi_val) {
    u32 r;
    asm("cvt.rn.bf16x2.f32 %0, %1, %2;" : "=r"(r) : "f"(hi_val), "f"(lo_val));
    return r;
}
__device__ __forceinline__ float f2bf_f(float x) {
    __nv_bfloat16 b = __float2bfloat16(x);
    return __bfloat162float(b);
}
__device__ __forceinline__ void mma16816(float& c0, float& c1, float& c2, float& c3,
                                         const u32* a, const u32* b) {
    asm volatile(
        "mma.sync.aligned.m16n8k16.row.col.f32.bf16.bf16.f32 "
        "{%0,%1,%2,%3}, {%4,%5,%6,%7}, {%8,%9}, {%0,%1,%2,%3};"
        : "+f"(c0), "+f"(c1), "+f"(c2), "+f"(c3)
        : "r"(a[0]), "r"(a[1]), "r"(a[2]), "r"(a[3]), "r"(b[0]), "r"(b[1]));
}
// release/acquire flag protocol (grid-sync pattern; no nanosleep, no fence.sc)
__device__ __forceinline__ int ld_acquire(const int* p) {
    int v;
    asm volatile("ld.acquire.gpu.global.s32 %0, [%1];" : "=r"(v) : "l"(p));
    return v;
}
__device__ __forceinline__ void st_release(int* p, int v) {
    asm volatile("st.release.gpu.global.s32 [%0], %1;" :: "l"(p), "r"(v) : "memory");
}

// ---------------- K0: zero accumulators + pipeline flags ----------------
__global__ void k_zero() {
    int t = threadIdx.x;
    if (t < CCH) { g_s1[t] = 0.0; g_q1[t] = 0.0; g_s2[t] = 0.0; g_q2[t] = 0.0; }
    for (int q = t; q < NLAY; q += blockDim.x) g_flag[q] = 0;
    for (int q = t; q < NLAY + 1; q += blockDim.x) g_done[q] = 0;
}

// ---------------- K1: conv1 + BN1 stats ----------------
__global__ void k_conv1(const float* __restrict__ x,
                        const float* __restrict__ w,
                        const float* __restrict__ bias) {
    int b = blockIdx.x;
    int tid = threadIdx.x;
    __shared__ float xs[CCH * TIN];
    __shared__ float ws[CCH * CCH * 5];
    __shared__ float bs[CCH];
    for (int i = tid; i < CCH * TIN; i += blockDim.x) xs[i] = x[b * CCH * TIN + i];
    if (tid < CCH * CCH * 5) ws[tid] = w[tid];
    if (tid < CCH) bs[tid] = bias[tid];
    __syncthreads();

    for (int c = 0; c < CCH; c++) {
        float s = 0.f, q = 0.f;
        for (int t = tid; t < T1; t += blockDim.x) {
            float a = bs[c];
            #pragma unroll
            for (int ci = 0; ci < CCH; ci++) {
                const float* xp = xs + ci * TIN + t;
                const float* wp = ws + (c * CCH + ci) * 5;
                #pragma unroll
                for (int k = 0; k < 5; k++) a = fmaf(xp[k], wp[k], a);
            }
            g_buf1[(b * CCH + c) * T1 + t] = a;
            s += a; q += a * a;
        }
        #pragma unroll
        for (int off = 16; off > 0; off >>= 1) {
            s += __shfl_down_sync(0xffffffffu, s, off);
            q += __shfl_down_sync(0xffffffffu, q, off);
        }
        if ((tid & 31) == 0) {
            atomicAdd(&g_s1[c], (double)s);
            atomicAdd(&g_q1[c], (double)q);
        }
    }
}

// ---------------- K2/K4: finalize BN ----------------
__global__ void k_bnfin(const float* __restrict__ gam,
                        const float* __restrict__ bet, int which) {
    int c = threadIdx.x;
    if (c < CCH) {
        double* S = which ? g_s2 : g_s1;
        double* Q = which ? g_q2 : g_q1;
        float* out = which ? g_bn2 : g_bn1;
        double n = which ? ((double)BATCH * T2) : ((double)BATCH * T1);
        double m = S[c] / n;
        double v = Q[c] / n - m * m;
        float sc = gam[c] * rsqrtf((float)v + 1e-5f);
        out[c] = sc;
        out[CCH + c] = bet[c] - (float)m * sc;
    }
}

// ---------------- K3: BN1+relu -> conv2 + BN2 stats ----------------
__global__ void k_conv2(const float* __restrict__ w,
                        const float* __restrict__ bias) {
    int b = blockIdx.x;
    int tid = threadIdx.x;
    __shared__ float xs[CCH * T1];
    __shared__ float ws[CCH * CCH * 5];
    __shared__ float bs[CCH];
    for (int i = tid; i < CCH * T1; i += blockDim.x) {
        int ci = i / T1;
        float v = g_buf1[b * CCH * T1 + i];
        xs[i] = fmaxf(fmaf(v, g_bn1[ci], g_bn1[CCH + ci]), 0.f);
    }
    if (tid < CCH * CCH * 5) ws[tid] = w[tid];
    if (tid < CCH) bs[tid] = bias[tid];
    __syncthreads();

    for (int c = 0; c < CCH; c++) {
        float s = 0.f, q = 0.f;
        for (int t = tid; t < T2; t += blockDim.x) {
            float a = bs[c];
            #pragma unroll
            for (int ci = 0; ci < CCH; ci++) {
                const float* xp = xs + ci * T1 + t;
                const float* wp = ws + (c * CCH + ci) * 5;
                #pragma unroll
                for (int k = 0; k < 5; k++) a = fmaf(xp[k], wp[k], a);
            }
            g_buf2[(b * CCH + c) * T2 + t] = a;
            s += a; q += a * a;
        }
        #pragma unroll
        for (int off = 16; off > 0; off >>= 1) {
            s += __shfl_down_sync(0xffffffffu, s, off);
            q += __shfl_down_sync(0xffffffffu, q, off);
        }
        if ((tid & 31) == 0) {
            atomicAdd(&g_s2[c], (double)s);
            atomicAdd(&g_q2[c], (double)q);
        }
    }
}

// ---------------- K5: BN2+relu -> attn -> seq [b][t][h] ----------------
__global__ void k_attn(const float* __restrict__ aw,
                       const float* __restrict__ ab) {
    int b = blockIdx.x;
    int tid = threadIdx.x;
    __shared__ float xs[CCH * T2];
    __shared__ float ws[HID * CCH];
    __shared__ float bs[HID];
    for (int i = tid; i < CCH * T2; i += blockDim.x) {
        int ci = i / T2;
        float v = g_buf2[b * CCH * T2 + i];
        xs[i] = fmaxf(fmaf(v, g_bn2[ci], g_bn2[CCH + ci]), 0.f);
    }
    if (tid < HID * CCH) ws[tid] = aw[tid];
    if (tid < HID) bs[tid] = ab[tid];
    __syncthreads();

    for (int idx = tid; idx < T2 * HID; idx += blockDim.x) {
        int t = idx / HID, h = idx % HID;
        float a = bs[h];
        #pragma unroll
        for (int c = 0; c < CCH; c++) a = fmaf(xs[c * T2 + t], ws[h * CCH + c], a);
        g_seq[(size_t)b * T2 * HID + idx] = fmaxf(a, 0.f);
    }
}

// ---------------- K6: layer-per-SM LSTM pipeline via mma.sync (bf16 hi/lo) ----------------
// Identical compute core to R13 (verified rel_err 5.3e-6); the ONLY change is
// the inter-layer handoff: busy-spin ld.acquire.gpu + st.release.gpu instead
// of __nanosleep polling + __threadfence (fence.sc.gpu).
__global__ void __launch_bounds__(NTH3, 1)
k_lstm3(const float* __restrict__ Wih, const float* __restrict__ Whh,
        const float* __restrict__ bih, const float* __restrict__ bhh) {
    extern __shared__ __align__(16) char sm[];
    int l = blockIdx.x;
    int tid = threadIdx.x;
    int lane = tid & 31, wp = tid >> 5;
    int kp = lane & 3, grp = lane >> 2;

    for (int q = tid; q < SG / 4; q += NTH3) ((u32*)sm)[q] = 0;
    for (int idx = tid; idx < 48 * 32; idx += NTH3) {
        int n = idx >> 5, k = idx & 31;
        float w = 0.f;
        if (k < 12)       w = Wih[((size_t)l * 48 + n) * 12 + k];
        else if (k < 24)  w = Whh[((size_t)l * 48 + n) * 12 + (k - 12)];
        else if (k == 24) w = bih[l * 48 + n] + bhh[l * 48 + n];
        if (!(n >= 24 && n < 36)) w *= 0.5f;
        __nv_bfloat16 hb = __float2bfloat16(w);
        __nv_bfloat16 lb = __float2bfloat16(w - __bfloat162float(hb));
        *(__nv_bfloat16*)(sm + SW_HI + n * 64 + k * 2) = hb;
        *(__nv_bfloat16*)(sm + SW_LO + n * 64 + k * 2) = lb;
    }
    __syncthreads();
    for (int b = tid; b < BATCH; b += NTH3)
        *(unsigned short*)(sm + SA_HI + b * 80 + 48) = 0x3F80;

    u32 Bh[6][2][2], Bl[6][2][2];
    #pragma unroll
    for (int nt = 0; nt < 6; nt++)
        #pragma unroll
        for (int kt = 0; kt < 2; kt++) {
            u32 off = (u32)(nt * 8 + grp) * 64 + kt * 32 + kp * 4;
            Bh[nt][kt][0] = *(u32*)(sm + SW_HI + off);
            Bh[nt][kt][1] = *(u32*)(sm + SW_HI + off + 16);
            Bl[nt][kt][0] = *(u32*)(sm + SW_LO + off);
            Bl[nt][kt][1] = *(u32*)(sm + SW_LO + off + 16);
        }

    float cst[2][HID], hv[2][HID];
    #pragma unroll
    for (int s = 0; s < 2; s++)
        #pragma unroll
        for (int u = 0; u < HID; u++) { cst[s][u] = 0.f; hv[s][u] = 0.f; }

    float* G = (float*)(sm + SG);
    __syncthreads();

    for (int t = 0; t < T2; t++) {
        // acquire upstream data + downstream ring credit (busy spin, acquire)
        if (tid == 0) {
            if (l > 0)
                while (ld_acquire(&g_flag[l - 1]) < t + 1) {}
            if (l < NLAY - 1 && t >= RD)
                while (ld_acquire(&g_done[l + 1]) < t - RD + 1) {}
        }
        __syncthreads();

        #pragma unroll
        for (int s = 0; s < 2; s++) {
            int b = tid + s * 256;
            float xv[HID];
            if (l == 0) {
                const float4* p = (const float4*)(g_seq + ((size_t)b * T2 + t) * HID);
                float4 A = p[0], B = p[1], C = p[2];
                xv[0]=A.x; xv[1]=A.y; xv[2]=A.z; xv[3]=A.w;
                xv[4]=B.x; xv[5]=B.y; xv[6]=B.z; xv[7]=B.w;
                xv[8]=C.x; xv[9]=C.y; xv[10]=C.z; xv[11]=C.w;
            } else {
                const float4* p = (const float4*)(g_ring +
                    (((size_t)(l - 1) * RD + (t & (RD - 1))) * BATCH + b) * HID);
                float4 A = __ldcg(p), B = __ldcg(p + 1), C = __ldcg(p + 2);
                xv[0]=A.x; xv[1]=A.y; xv[2]=A.z; xv[3]=A.w;
                xv[4]=B.x; xv[5]=B.y; xv[6]=B.z; xv[7]=B.w;
                xv[8]=C.x; xv[9]=C.y; xv[10]=C.z; xv[11]=C.w;
            }
            char* rh = sm + SA_HI + (size_t)b * 80;
            char* rl = sm + SA_LO + (size_t)b * 80;
            #pragma unroll
            for (int q = 0; q < 6; q++) {
                float v0 = xv[2 * q], v1 = xv[2 * q + 1];
                *(u32*)(rh + 4 * q) = pkbf2(v0, v1);
                *(u32*)(rl + 4 * q) = pkbf2(v0 - f2bf_f(v0), v1 - f2bf_f(v1));
            }
            #pragma unroll
            for (int q = 0; q < 6; q++) {
                float v0 = hv[s][2 * q], v1 = hv[s][2 * q + 1];
                *(u32*)(rh + 24 + 4 * q) = pkbf2(v0, v1);
                *(u32*)(rl + 24 + 4 * q) = pkbf2(v0 - f2bf_f(v0), v1 - f2bf_f(v1));
            }
        }
        __syncthreads();

        // upstream ring slot consumed -> publish credit (release)
        if (tid == 0 && l > 0) st_release(&g_done[l], t + 1);

        #pragma unroll
        for (int mt = 0; mt < 4; mt++) {
            int r0 = wp * 64 + mt * 16 + grp, r1 = r0 + 8;
            u32 ah[2][4], al[2][4];
            #pragma unroll
            for (int kt = 0; kt < 2; kt++) {
                u32 o0 = (u32)r0 * 80 + kt * 32 + kp * 4;
                u32 o1 = (u32)r1 * 80 + kt * 32 + kp * 4;
                ah[kt][0] = *(u32*)(sm + SA_HI + o0);
                ah[kt][1] = *(u32*)(sm + SA_HI + o1);
                ah[kt][2] = *(u32*)(sm + SA_HI + o0 + 16);
                ah[kt][3] = *(u32*)(sm + SA_HI + o1 + 16);
                al[kt][0] = *(u32*)(sm + SA_LO + o0);
                al[kt][1] = *(u32*)(sm + SA_LO + o1);
                al[kt][2] = *(u32*)(sm + SA_LO + o0 + 16);
                al[kt][3] = *(u32*)(sm + SA_LO + o1 + 16);
            }
            #pragma unroll
            for (int nt = 0; nt < 6; nt++) {
                float c0 = 0.f, c1 = 0.f, c2 = 0.f, c3 = 0.f;
                mma16816(c0, c1, c2, c3, ah[0], Bh[nt][0]);
                mma16816(c0, c1, c2, c3, ah[1], Bh[nt][1]);
                mma16816(c0, c1, c2, c3, ah[0], Bl[nt][0]);
                mma16816(c0, c1, c2, c3, ah[1], Bl[nt][1]);
                mma16816(c0, c1, c2, c3, al[0], Bh[nt][0]);
                mma16816(c0, c1, c2, c3, al[1], Bh[nt][1]);
                int n0 = nt * 8 + kp * 2;
                G[(size_t)n0 * 513 + r0]       = c0;
                G[(size_t)(n0 + 1) * 513 + r0] = c1;
                G[(size_t)n0 * 513 + r1]       = c2;
                G[(size_t)(n0 + 1) * 513 + r1] = c3;
            }
        }
        __syncthreads();

        #pragma unroll
        for (int s = 0; s < 2; s++) {
            int b = tid + s * 256;
            #pragma unroll
            for (int u = 0; u < HID; u++) {
                float gi = sigm_pre(G[(size_t)u * 513 + b]);
                float gf = sigm_pre(G[(size_t)(12 + u) * 513 + b]);
                float gg = tanh_t (G[(size_t)(24 + u) * 513 + b]);
                float go = sigm_pre(G[(size_t)(36 + u) * 513 + b]);
                cst[s][u] = fmaf(gf, cst[s][u], gi * gg);
                hv[s][u] = go * tanh_t(cst[s][u]);
            }
            if (l < NLAY - 1) {
                float4* p = (float4*)(g_ring +
                    (((size_t)l * RD + (t & (RD - 1))) * BATCH + b) * HID);
                __stcg(p,     make_float4(hv[s][0], hv[s][1], hv[s][2],  hv[s][3]));
                __stcg(p + 1, make_float4(hv[s][4], hv[s][5], hv[s][6],  hv[s][7]));
                __stcg(p + 2, make_float4(hv[s][8], hv[s][9], hv[s][10], hv[s][11]));
            }
            if (t == T2 - 1) {
                float4* p = (float4*)(g_hid + ((size_t)b * NLAY + l) * HID);
                p[0] = make_float4(hv[s][0], hv[s][1], hv[s][2],  hv[s][3]);
                p[1] = make_float4(hv[s][4], hv[s][5], hv[s][6],  hv[s][7]);
                p[2] = make_float4(hv[s][8], hv[s][9], hv[s][10], hv[s][11]);
            }
        }
        __syncthreads();
        // release this tick to downstream
        if (tid == 0 && l < NLAY - 1) st_release(&g_flag[l], t + 1);
    }
}

// ---------------- K7: MLP head -> (z, out, mu, log_var) ----------------
__global__ void k_head(const float* __restrict__ eps,
                       const float* __restrict__ l1w, const float* __restrict__ l1b,
                       const float* __restrict__ l2w, const float* __restrict__ l2b,
                       const float* __restrict__ muw, const float* __restrict__ mub,
                       const float* __restrict__ lvw, const float* __restrict__ lvb,
                       float* __restrict__ out) {
    __shared__ float W1[144], W2[144], WM[144], WV[144];
    __shared__ float B1[12], B2[12], BM[12], BV[12];
    int tid = threadIdx.x;
    for (int q = tid; q < 144; q += blockDim.x) {
        W1[q] = l1w[q]; W2[q] = l2w[q]; WM[q] = muw[q]; WV[q] = lvw[q];
    }
    if (tid < 12) { B1[tid] = l1b[tid]; B2[tid] = l2b[tid]; BM[tid] = mub[tid]; BV[tid] = lvb[tid]; }
    __syncthreads();

    int row = blockIdx.x * blockDim.x + tid;
    if (row >= BATCH * NLAY) return;
    const float* hp = g_hid + (size_t)row * HID;
    float h[HID], v1[HID], v2[HID];
    {
        float4 a = *(const float4*)(hp);
        float4 bq = *(const float4*)(hp + 4);
        float4 cq = *(const float4*)(hp + 8);
        h[0]=a.x; h[1]=a.y; h[2]=a.z; h[3]=a.w; h[4]=bq.x; h[5]=bq.y; h[6]=bq.z; h[7]=bq.w;
        h[8]=cq.x; h[9]=cq.y; h[10]=cq.z; h[11]=cq.w;
    }
    #pragma unroll
    for (int r = 0; r < HID; r++) {
        float a = B1[r];
        #pragma unroll
        for (int m = 0; m < HID; m++) a = fmaf(W1[r * HID + m], h[m], a);
        v1[r] = fmaxf(a, 0.f);
    }
    #pragma unroll
    for (int r = 0; r < HID; r++) {
        float a = B2[r];
        #pragma unroll
        for (int m = 0; m < HID; m++) a = fmaf(W2[r * HID + m], v1[m], a);
        v2[r] = fmaxf(a, 0.f);
    }
    #pragma unroll
    for (int r = 0; r < HID; r++) {
        float mu = BM[r], lv = BV[r];
        #pragma unroll
        for (int m = 0; m < HID; m++) {
            mu = fmaf(WM[r * HID + m], v2[m], mu);
            lv = fmaf(WV[r * HID + m], v2[m], lv);
        }
        float e = eps[(size_t)row * HID + r];
        float z = fmaf(__expf(0.5f * lv), e, mu);
        size_t idx = (size_t)row * HID + r;
        out[idx]                    = z;
        out[NOUT + idx]             = v2[r];
        out[2 * (size_t)NOUT + idx] = mu;
        out[3 * (size_t)NOUT + idx] = lv;
    }
}

// ---------------- launcher ----------------
extern "C" void kernel_launch(void* const* d_in, const int* in_sizes, int n_in,
                              void* d_out, int out_size) {
    const float* x    = (const float*)d_in[0];
    const float* eps  = (const float*)d_in[1];
    const float* c1w  = (const float*)d_in[2];
    const float* c1b  = (const float*)d_in[3];
    const float* c2w  = (const float*)d_in[4];
    const float* c2b  = (const float*)d_in[5];
    const float* bn1g = (const float*)d_in[6];
    const float* bn1b = (const float*)d_in[7];
    const float* bn2g = (const float*)d_in[8];
    const float* bn2b = (const float*)d_in[9];
    const float* aw   = (const float*)d_in[10];
    const float* ab   = (const float*)d_in[11];
    const float* Wih  = (const float*)d_in[12];
    const float* Whh  = (const float*)d_in[13];
    const float* bih  = (const float*)d_in[14];
    const float* bhh  = (const float*)d_in[15];
    const float* l1w  = (const float*)d_in[16];
    const float* l1b  = (const float*)d_in[17];
    const float* l2w  = (const float*)d_in[18];
    const float* l2b  = (const float*)d_in[19];
    const float* muw  = (const float*)d_in[20];
    const float* mub  = (const float*)d_in[21];
    const float* lvw  = (const float*)d_in[22];
    const float* lvb  = (const float*)d_in[23];

    cudaFuncSetAttribute(k_lstm3, cudaFuncAttributeMaxDynamicSharedMemorySize,
                         LSTM3_SMEM);

    k_zero<<<1, 256>>>();
    k_conv1<<<BATCH, 256>>>(x, c1w, c1b);
    k_bnfin<<<1, 32>>>(bn1g, bn1b, 0);
    k_conv2<<<BATCH, 256>>>(c2w, c2b);
    k_bnfin<<<1, 32>>>(bn2g, bn2b, 1);
    k_attn<<<BATCH, 256>>>(aw, ab);
    k_lstm3<<<NLAY, NTH3, LSTM3_SMEM>>>(Wih, Whh, bih, bhh);
    k_head<<<(BATCH * NLAY) / 128, 128>>>(eps, l1w, l1b, l2w, l2b, muw, mub, lvw, lvb,
                                          (float*)d_out);
}

// round 15
// speedup vs baseline: 1.7560x; 1.7560x over previous
#include <cuda_runtime.h>
#include <math.h>

// ---------------- problem constants ----------------
#define BATCH 512
#define TIN   512
#define CCH   6
#define HID   12
#define NLAY  120
#define T1    508        // after conv1 (k=5 VALID)
#define T2    504        // after conv2
#define GL    10         // layers per pipeline group
#define NGRP  12         // 120 / 10
#define NTH   120        // GL * HID threads in LSTM block
#define NPAIR 256        // batch pairs (2 per block)
#define NOUT  (BATCH*NLAY*HID)   // 737280 per output tensor

typedef unsigned long long u64;

// dynamic smem for k_lstm (all u64):
//   seq  : T2*HID     packed (b0,b1)      = 48384 B
//   hbuf : 2*GL*HID   h ring              =  1920 B
//   bias : NTH*4      packed gate biases  =  3840 B
#define SEQ_U   (T2*HID)
#define HBUF_U  (2*GL*HID)
#define BIAS_U  (NTH*4)
#define LSTM_SMEM_BYTES ((SEQ_U + HBUF_U + BIAS_U) * 8)

// ---------------- device scratch (static, no allocation) ----------------
__device__ double g_s1[CCH], g_q1[CCH], g_s2[CCH], g_q2[CCH];
__device__ float  g_bn1[2*CCH];   // scale[6], shift[6]
__device__ float  g_bn2[2*CCH];
__device__ float  g_buf1[BATCH*CCH*T1];
__device__ float  g_buf2[BATCH*CCH*T2];
__device__ float  g_seq [BATCH*T2*HID];   // pair-interleaved: [pair][t][h][lane2]
__device__ float  g_hid [BATCH*NLAY*HID];

// ---------------- f32x2 helpers (b64 operands -> "l" constraint) ----------------
__device__ __forceinline__ u64 ffma2(u64 a, u64 b, u64 c) {
    u64 d;
    asm("fma.rn.f32x2 %0, %1, %2, %3;" : "=l"(d) : "l"(a), "l"(b), "l"(c));
    return d;
}
__device__ __forceinline__ u64 pack2(float x, float y) {
    u64 d;
    asm("mov.b64 %0, {%1, %2};" : "=l"(d) : "f"(x), "f"(y));
    return d;
}
__device__ __forceinline__ void unpack2(u64 d, float& x, float& y) {
    asm("mov.b64 {%0, %1}, %2;" : "=f"(x), "=f"(y) : "l"(d));
}

// ---------------- activation helpers ----------------
__device__ __forceinline__ float tanh_t(float x) {
    float y;
    asm("tanh.approx.f32 %0, %1;" : "=f"(y) : "f"(x));
    return y;
}
// sigmoid with the 0.5*x folded into weights/bias (acc already = 0.5*x).
// 0.5 scaling is a power of 2 -> bit-identical to fma(0.5, tanh(0.5*x), 0.5).
__device__ __forceinline__ float sigm_pre(float hx) {
    return fmaf(0.5f, tanh_t(hx), 0.5f);
}

// ---------------- K0: zero BN stat accumulators ----------------
__global__ void k_zero() {
    int t = threadIdx.x;
    if (t < CCH) { g_s1[t] = 0.0; g_q1[t] = 0.0; g_s2[t] = 0.0; g_q2[t] = 0.0; }
}

// ---------------- K1: conv1 + BN1 stats ----------------
__global__ void k_conv1(const float* __restrict__ x,
                        const float* __restrict__ w,
                        const float* __restrict__ bias) {
    int b = blockIdx.x;
    int tid = threadIdx.x;
    __shared__ float xs[CCH * TIN];
    __shared__ float ws[CCH * CCH * 5];
    __shared__ float bs[CCH];
    for (int i = tid; i < CCH * TIN; i += blockDim.x) xs[i] = x[b * CCH * TIN + i];
    if (tid < CCH * CCH * 5) ws[tid] = w[tid];
    if (tid < CCH) bs[tid] = bias[tid];
    __syncthreads();

    for (int c = 0; c < CCH; c++) {
        float s = 0.f, q = 0.f;
        for (int t = tid; t < T1; t += blockDim.x) {
            float a = bs[c];
            #pragma unroll
            for (int ci = 0; ci < CCH; ci++) {
                const float* xp = xs + ci * TIN + t;
                const float* wp = ws + (c * CCH + ci) * 5;
                #pragma unroll
                for (int k = 0; k < 5; k++) a = fmaf(xp[k], wp[k], a);
            }
            g_buf1[(b * CCH + c) * T1 + t] = a;
            s += a; q += a * a;
        }
        #pragma unroll
        for (int off = 16; off > 0; off >>= 1) {
            s += __shfl_down_sync(0xffffffffu, s, off);
            q += __shfl_down_sync(0xffffffffu, q, off);
        }
        if ((tid & 31) == 0) {
            atomicAdd(&g_s1[c], (double)s);
            atomicAdd(&g_q1[c], (double)q);
        }
    }
}

// ---------------- K2/K4: finalize BN scale/shift ----------------
__global__ void k_bnfin(const float* __restrict__ gam,
                        const float* __restrict__ bet, int which) {
    int c = threadIdx.x;
    if (c < CCH) {
        double* S = which ? g_s2 : g_s1;
        double* Q = which ? g_q2 : g_q1;
        float* out = which ? g_bn2 : g_bn1;
        double n = which ? ((double)BATCH * T2) : ((double)BATCH * T1);
        double m = S[c] / n;
        double v = Q[c] / n - m * m;
        float sc = gam[c] * rsqrtf((float)v + 1e-5f);
        out[c] = sc;
        out[CCH + c] = bet[c] - (float)m * sc;
    }
}

// ---------------- K3: BN1+relu -> conv2 + BN2 stats ----------------
__global__ void k_conv2(const float* __restrict__ w,
                        const float* __restrict__ bias) {
    int b = blockIdx.x;
    int tid = threadIdx.x;
    __shared__ float xs[CCH * T1];
    __shared__ float ws[CCH * CCH * 5];
    __shared__ float bs[CCH];
    for (int i = tid; i < CCH * T1; i += blockDim.x) {
        int ci = i / T1;
        float v = g_buf1[b * CCH * T1 + i];
        xs[i] = fmaxf(fmaf(v, g_bn1[ci], g_bn1[CCH + ci]), 0.f);
    }
    if (tid < CCH * CCH * 5) ws[tid] = w[tid];
    if (tid < CCH) bs[tid] = bias[tid];
    __syncthreads();

    for (int c = 0; c < CCH; c++) {
        float s = 0.f, q = 0.f;
        for (int t = tid; t < T2; t += blockDim.x) {
            float a = bs[c];
            #pragma unroll
            for (int ci = 0; ci < CCH; ci++) {
                const float* xp = xs + ci * T1 + t;
                const float* wp = ws + (c * CCH + ci) * 5;
                #pragma unroll
                for (int k = 0; k < 5; k++) a = fmaf(xp[k], wp[k], a);
            }
            g_buf2[(b * CCH + c) * T2 + t] = a;
            s += a; q += a * a;
        }
        #pragma unroll
        for (int off = 16; off > 0; off >>= 1) {
            s += __shfl_down_sync(0xffffffffu, s, off);
            q += __shfl_down_sync(0xffffffffu, q, off);
        }
        if ((tid & 31) == 0) {
            atomicAdd(&g_s2[c], (double)s);
            atomicAdd(&g_q2[c], (double)q);
        }
    }
}

// ---------------- K5: BN2+relu -> attn -> seq (batch-pair interleaved) ----------------
__global__ void k_attn(const float* __restrict__ aw,
                       const float* __restrict__ ab) {
    int b = blockIdx.x;
    int tid = threadIdx.x;
    __shared__ float xs[CCH * T2];
    __shared__ float ws[HID * CCH];
    __shared__ float bs[HID];
    for (int i = tid; i < CCH * T2; i += blockDim.x) {
        int ci = i / T2;
        float v = g_buf2[b * CCH * T2 + i];
        xs[i] = fmaxf(fmaf(v, g_bn2[ci], g_bn2[CCH + ci]), 0.f);
    }
    if (tid < HID * CCH) ws[tid] = aw[tid];
    if (tid < HID) bs[tid] = ab[tid];
    __syncthreads();

    size_t base = ((size_t)(b >> 1)) * T2 * HID * 2 + (b & 1);
    for (int idx = tid; idx < T2 * HID; idx += blockDim.x) {
        int t = idx / HID, h = idx % HID;
        float a = bs[h];
        #pragma unroll
        for (int c = 0; c < CCH; c++) a = fmaf(xs[c * T2 + t], ws[h * CCH + c], a);
        g_seq[base + (size_t)idx * 2] = fmaxf(a, 0.f);
    }
}

// ---------------- K6: 120-layer LSTM, 2 batches/block, 2 blocks/SM ----------------
// R10 champion + two bit-exact instruction cuts:
//   1. sigmoid 0.5-prescale folded into packed weights/bias (power-of-2 =>
//      bit-identical); deletes the inner 0.5*x mul of each sigmoid.
//   2. tick loop unrolled x2 with literal ring parity (no p = k&1, half the
//      loop increment/branch overhead). Barriers stay block-uniform.
#define LSTM_TICK(PAR, KIDX)                                                  \
    {                                                                         \
        int t = (KIDX) - j;                                                   \
        if ((unsigned)t < (unsigned)T2) {                                     \
            const u64* xp = (j == 0) ? (seq_s + t * HID)                      \
                                     : (hbuf + (((PAR) ^ 1) * GL + (j - 1)) * HID); \
            const u64* hp = hbuf + (((PAR) ^ 1) * GL + j) * HID;              \
            u64 a0 = bias_s[tid * 4 + 0], a1 = bias_s[tid * 4 + 1];           \
            u64 a2 = bias_s[tid * 4 + 2], a3 = bias_s[tid * 4 + 3];           \
            u64 v[HID];                                                       \
            _Pragma("unroll")                                                 \
            for (int q = 0; q < HID / 2; q++) {                               \
                ulonglong2 tv = ((const ulonglong2*)xp)[q];                   \
                v[2 * q] = tv.x; v[2 * q + 1] = tv.y;                         \
            }                                                                 \
            _Pragma("unroll")                                                 \
            for (int m = 0; m < HID; m++) {                                   \
                u64 xm = v[m];                                                \
                a0 = ffma2(wih2[0][m], xm, a0);                               \
                a1 = ffma2(wih2[1][m], xm, a1);                               \
                a2 = ffma2(wih2[2][m], xm, a2);                               \
                a3 = ffma2(wih2[3][m], xm, a3);                               \
            }                                                                 \
            _Pragma("unroll")                                                 \
            for (int q = 0; q < HID / 2; q++) {                               \
                ulonglong2 tv = ((const ulonglong2*)hp)[q];                   \
                v[2 * q] = tv.x; v[2 * q + 1] = tv.y;                         \
            }                                                                 \
            _Pragma("unroll")                                                 \
            for (int m = 0; m < HID; m++) {                                   \
                u64 hm = v[m];                                                \
                a0 = ffma2(whh2[0][m], hm, a0);                               \
                a1 = ffma2(whh2[1][m], hm, a1);                               \
                a2 = ffma2(whh2[2][m], hm, a2);                               \
                a3 = ffma2(whh2[3][m], hm, a3);                               \
            }                                                                 \
            float g0x, g0y, g1x, g1y, g2x, g2y, g3x, g3y;                     \
            unpack2(a0, g0x, g0y);                                            \
            unpack2(a1, g1x, g1y);                                            \
            unpack2(a2, g2x, g2y);                                            \
            unpack2(a3, g3x, g3y);                                            \
            float gi = sigm_pre(g0x), gf = sigm_pre(g1x);                     \
            float gg = tanh_t(g2x),   go = sigm_pre(g3x);                     \
            c0 = gf * c0 + gi * gg;                                           \
            float h0 = go * tanh_t(c0);                                       \
            gi = sigm_pre(g0y); gf = sigm_pre(g1y);                           \
            gg = tanh_t(g2y);   go = sigm_pre(g3y);                           \
            c1 = gf * c1 + gi * gg;                                           \
            float h1 = go * tanh_t(c1);                                       \
            u64 hpk = pack2(h0, h1);                                          \
            hbuf[((PAR) * GL + j) * HID + i] = hpk;                           \
            if (j == GL - 1) seq_s[t * HID + i] = hpk;                        \
            if (t == T2 - 1) {                                                \
                g_hid[((size_t)b0 * NLAY + l) * HID + i] = h0;                \
                g_hid[((size_t)b1 * NLAY + l) * HID + i] = h1;                \
            }                                                                 \
        }                                                                     \
    }

__global__ void __launch_bounds__(NTH, 2)
k_lstm(const float* __restrict__ Wih, const float* __restrict__ Whh,
       const float* __restrict__ bih, const float* __restrict__ bhh) {
    extern __shared__ __align__(16) u64 smem[];
    u64* seq_s  = smem;                    // [T2*HID] packed (b0,b1)
    u64* hbuf   = smem + SEQ_U;            // [2][GL][HID]
    u64* bias_s = smem + SEQ_U + HBUF_U;   // [NTH][4]

    int pair = blockIdx.x;
    int b0 = pair * 2, b1 = b0 + 1;
    int tid = threadIdx.x;
    int j = tid / HID;   // local layer in group
    int i = tid % HID;   // hidden unit

    // load this pair's interleaved sequence into shared (48 KB, float4)
    {
        const float4* src = (const float4*)(g_seq + (size_t)pair * T2 * HID * 2);
        float4* dst = (float4*)seq_s;
        for (int q = tid; q < (T2 * HID * 2) / 4; q += NTH) dst[q] = src[q];
    }

    for (int grp = 0; grp < NGRP; grp++) {
        int l = grp * GL + j;
        // zero h ring (h0 = c0 = 0)
        for (int q = tid; q < HBUF_U; q += NTH) hbuf[q] = 0ull;

        // pack this thread's 4 gate rows; sigmoid rows (0,1,3) pre-scaled 0.5
        u64 wih2[4][HID], whh2[4][HID];
        {
            const float* Wi = Wih + (size_t)l * 48 * HID;
            const float* Wh = Whh + (size_t)l * 48 * HID;
            #pragma unroll
            for (int r = 0; r < 4; r++) {
                int row = r * HID + i;
                float sc = (r == 2) ? 1.0f : 0.5f;
                #pragma unroll
                for (int m = 0; m < HID; m++) {
                    float wi = Wi[row * HID + m] * sc;
                    float wh = Wh[row * HID + m] * sc;
                    wih2[r][m] = pack2(wi, wi);
                    whh2[r][m] = pack2(wh, wh);
                }
                float bb = (bih[l * 48 + row] + bhh[l * 48 + row]) * sc;
                bias_s[tid * 4 + r] = pack2(bb, bb);
            }
        }
        float c0 = 0.f, c1 = 0.f;
        __syncthreads();

        // T2 + GL - 1 = 513 ticks, unrolled by 2 with literal parity
        for (int k = 0; k < T2 + GL - 1; k += 2) {
            LSTM_TICK(0, k);
            __syncthreads();
            if (k + 1 < T2 + GL - 1) {     // block-uniform guard
                LSTM_TICK(1, k + 1);
            }
            __syncthreads();
        }
        __syncthreads();
    }
}
#undef LSTM_TICK

// ---------------- K7: MLP head -> (z, out, mu, log_var) ----------------
__global__ void k_head(const float* __restrict__ eps,
                       const float* __restrict__ l1w, const float* __restrict__ l1b,
                       const float* __restrict__ l2w, const float* __restrict__ l2b,
                       const float* __restrict__ muw, const float* __restrict__ mub,
                       const float* __restrict__ lvw, const float* __restrict__ lvb,
                       float* __restrict__ out) {
    __shared__ float W1[144], W2[144], WM[144], WV[144];
    __shared__ float B1[12], B2[12], BM[12], BV[12];
    int tid = threadIdx.x;
    for (int q = tid; q < 144; q += blockDim.x) {
        W1[q] = l1w[q]; W2[q] = l2w[q]; WM[q] = muw[q]; WV[q] = lvw[q];
    }
    if (tid < 12) { B1[tid] = l1b[tid]; B2[tid] = l2b[tid]; BM[tid] = mub[tid]; BV[tid] = lvb[tid]; }
    __syncthreads();

    int row = blockIdx.x * blockDim.x + tid;       // (b*120 + l)
    if (row >= BATCH * NLAY) return;
    const float* hp = g_hid + (size_t)row * HID;
    float h[HID], v1[HID], v2[HID];
    {
        float4 a = *(const float4*)(hp);
        float4 bq = *(const float4*)(hp + 4);
        float4 cq = *(const float4*)(hp + 8);
        h[0]=a.x; h[1]=a.y; h[2]=a.z; h[3]=a.w; h[4]=bq.x; h[5]=bq.y; h[6]=bq.z; h[7]=bq.w;
        h[8]=cq.x; h[9]=cq.y; h[10]=cq.z; h[11]=cq.w;
    }
    #pragma unroll
    for (int r = 0; r < HID; r++) {
        float a = B1[r];
        #pragma unroll
        for (int m = 0; m < HID; m++) a = fmaf(W1[r * HID + m], h[m], a);
        v1[r] = fmaxf(a, 0.f);
    }
    #pragma unroll
    for (int r = 0; r < HID; r++) {
        float a = B2[r];
        #pragma unroll
        for (int m = 0; m < HID; m++) a = fmaf(W2[r * HID + m], v1[m], a);
        v2[r] = fmaxf(a, 0.f);
    }
    #pragma unroll
    for (int r = 0; r < HID; r++) {
        float mu = BM[r], lv = BV[r];
        #pragma unroll
        for (int m = 0; m < HID; m++) {
            mu = fmaf(WM[r * HID + m], v2[m], mu);
            lv = fmaf(WV[r * HID + m], v2[m], lv);
        }
        float e = eps[(size_t)row * HID + r];
        float z = fmaf(__expf(0.5f * lv), e, mu);
        size_t idx = (size_t)row * HID + r;
        out[idx]              = z;
        out[NOUT + idx]       = v2[r];
        out[2 * (size_t)NOUT + idx] = mu;
        out[3 * (size_t)NOUT + idx] = lv;
    }
}

// ---------------- launcher ----------------
extern "C" void kernel_launch(void* const* d_in, const int* in_sizes, int n_in,
                              void* d_out, int out_size) {
    const float* x    = (const float*)d_in[0];
    const float* eps  = (const float*)d_in[1];
    const float* c1w  = (const float*)d_in[2];
    const float* c1b  = (const float*)d_in[3];
    const float* c2w  = (const float*)d_in[4];
    const float* c2b  = (const float*)d_in[5];
    const float* bn1g = (const float*)d_in[6];
    const float* bn1b = (const float*)d_in[7];
    const float* bn2g = (const float*)d_in[8];
    const float* bn2b = (const float*)d_in[9];
    const float* aw   = (const float*)d_in[10];
    const float* ab   = (const float*)d_in[11];
    const float* Wih  = (const float*)d_in[12];
    const float* Whh  = (const float*)d_in[13];
    const float* bih  = (const float*)d_in[14];
    const float* bhh  = (const float*)d_in[15];
    const float* l1w  = (const float*)d_in[16];
    const float* l1b  = (const float*)d_in[17];
    const float* l2w  = (const float*)d_in[18];
    const float* l2b  = (const float*)d_in[19];
    const float* muw  = (const float*)d_in[20];
    const float* mub  = (const float*)d_in[21];
    const float* lvw  = (const float*)d_in[22];
    const float* lvb  = (const float*)d_in[23];

    cudaFuncSetAttribute(k_lstm, cudaFuncAttributeMaxDynamicSharedMemorySize,
                         LSTM_SMEM_BYTES);

    k_zero<<<1, 32>>>();
    k_conv1<<<BATCH, 256>>>(x, c1w, c1b);
    k_bnfin<<<1, 32>>>(bn1g, bn1b, 0);
    k_conv2<<<BATCH, 256>>>(c2w, c2b);
    k_bnfin<<<1, 32>>>(bn2g, bn2b, 1);
    k_attn<<<BATCH, 256>>>(aw, ab);
    k_lstm<<<NPAIR, NTH, LSTM_SMEM_BYTES>>>(Wih, Whh, bih, bhh);
    k_head<<<(BATCH * NLAY) / 128, 128>>>(eps, l1w, l1b, l2w, l2b, muw, mub, lvw, lvb,
                                          (float*)d_out);
}

// round 16
// speedup vs baseline: 1.9570x; 1.1144x over previous
#include <cuda_runtime.h>
#include <math.h>

// ---------------- problem constants ----------------
#define BATCH 512
#define TIN   512
#define CCH   6
#define HID   12
#define NLAY  120
#define T1    508        // after conv1 (k=5 VALID)
#define T2    504        // after conv2
#define GL    10         // layers per pipeline group
#define NGRP  12         // 120 / 10
#define NTH   120        // GL * HID threads in LSTM block
#define NPAIR 256        // batch pairs (2 per block)
#define NOUT  (BATCH*NLAY*HID)   // 737280 per output tensor

typedef unsigned long long u64;

// dynamic smem for k_lstm (all u64):
#define SEQ_U   (T2*HID)
#define HBUF_U  (2*GL*HID)
#define BIAS_U  (NTH*4)
#define LSTM_SMEM_BYTES ((SEQ_U + HBUF_U + BIAS_U) * 8)

// ---------------- device scratch (static, no allocation) ----------------
__device__ double g_s1[CCH], g_q1[CCH], g_s2[CCH], g_q2[CCH];
__device__ float  g_buf1[BATCH*CCH*T1];
__device__ float  g_buf2[BATCH*CCH*T2];
__device__ float  g_seq [BATCH*T2*HID];   // pair-interleaved: [pair][t][h][lane2]
__device__ float  g_hid [BATCH*NLAY*HID];

// ---------------- f32x2 helpers (b64 operands -> "l" constraint) ----------------
__device__ __forceinline__ u64 ffma2(u64 a, u64 b, u64 c) {
    u64 d;
    asm("fma.rn.f32x2 %0, %1, %2, %3;" : "=l"(d) : "l"(a), "l"(b), "l"(c));
    return d;
}
__device__ __forceinline__ u64 pack2(float x, float y) {
    u64 d;
    asm("mov.b64 %0, {%1, %2};" : "=l"(d) : "f"(x), "f"(y));
    return d;
}
__device__ __forceinline__ void unpack2(u64 d, float& x, float& y) {
    asm("mov.b64 {%0, %1}, %2;" : "=f"(x), "=f"(y) : "l"(d));
}

// ---------------- activation helpers ----------------
__device__ __forceinline__ float tanh_t(float x) {
    float y;
    asm("tanh.approx.f32 %0, %1;" : "=f"(y) : "f"(x));
    return y;
}
__device__ __forceinline__ float sigm_t(float x) {
    return fmaf(0.5f, tanh_t(0.5f * x), 0.5f);
}

// BN scale/shift from raw stats (computed redundantly per block; 6 channels)
__device__ __forceinline__ void bn_coeff(const double* S, const double* Q, double n,
                                         const float* gam, const float* bet,
                                         float* sc_out, float* sh_out, int c) {
    double m = S[c] / n;
    double v = Q[c] / n - m * m;
    float sc = gam[c] * rsqrtf((float)v + 1e-5f);
    sc_out[c] = sc;
    sh_out[c] = bet[c] - (float)m * sc;
}

// ---------------- K0: zero BN stat accumulators ----------------
__global__ void k_zero() {
    int t = threadIdx.x;
    if (t < CCH) { g_s1[t] = 0.0; g_q1[t] = 0.0; g_s2[t] = 0.0; g_q2[t] = 0.0; }
}

// ---------------- K1: conv1 + BN1 stats (block-reduced atomics) ----------------
__global__ void k_conv1(const float* __restrict__ x,
                        const float* __restrict__ w,
                        const float* __restrict__ bias) {
    int b = blockIdx.x;
    int tid = threadIdx.x;
    int wid = tid >> 5;
    __shared__ float xs[CCH * TIN];
    __shared__ float ws[CCH * CCH * 5];
    __shared__ float bs[CCH];
    __shared__ float sw[CCH][8], qw[CCH][8];   // per-warp partials
    for (int i = tid; i < CCH * TIN; i += blockDim.x) xs[i] = x[b * CCH * TIN + i];
    if (tid < CCH * CCH * 5) ws[tid] = w[tid];
    if (tid < CCH) bs[tid] = bias[tid];
    __syncthreads();

    for (int c = 0; c < CCH; c++) {
        float s = 0.f, q = 0.f;
        for (int t = tid; t < T1; t += blockDim.x) {
            float a = bs[c];
            #pragma unroll
            for (int ci = 0; ci < CCH; ci++) {
                const float* xp = xs + ci * TIN + t;
                const float* wp = ws + (c * CCH + ci) * 5;
                #pragma unroll
                for (int k = 0; k < 5; k++) a = fmaf(xp[k], wp[k], a);
            }
            g_buf1[(b * CCH + c) * T1 + t] = a;
            s += a; q += a * a;
        }
        #pragma unroll
        for (int off = 16; off > 0; off >>= 1) {
            s += __shfl_down_sync(0xffffffffu, s, off);
            q += __shfl_down_sync(0xffffffffu, q, off);
        }
        if ((tid & 31) == 0) { sw[c][wid] = s; qw[c][wid] = q; }
    }
    __syncthreads();
    // one atomic per (channel, stat) per block
    if (tid < CCH) {
        float s = 0.f, q = 0.f;
        #pragma unroll
        for (int wq = 0; wq < 8; wq++) { s += sw[tid][wq]; q += qw[tid][wq]; }
        atomicAdd(&g_s1[tid], (double)s);
        atomicAdd(&g_q1[tid], (double)q);
    }
}

// ---------------- K3: BN1+relu -> conv2 + BN2 stats (bnfin folded in) ----------------
__global__ void k_conv2(const float* __restrict__ w,
                        const float* __restrict__ bias,
                        const float* __restrict__ bn1g,
                        const float* __restrict__ bn1b) {
    int b = blockIdx.x;
    int tid = threadIdx.x;
    int wid = tid >> 5;
    __shared__ float xs[CCH * T1];
    __shared__ float ws[CCH * CCH * 5];
    __shared__ float bs[CCH];
    __shared__ float bsc[CCH], bsh[CCH];
    __shared__ float sw[CCH][8], qw[CCH][8];
    if (tid < CCH)
        bn_coeff(g_s1, g_q1, (double)BATCH * T1, bn1g, bn1b, bsc, bsh, tid);
    if (tid < CCH * CCH * 5) ws[tid] = w[tid];
    if (tid >= CCH * CCH * 5 && tid < CCH * CCH * 5 + CCH)
        bs[tid - CCH * CCH * 5] = bias[tid - CCH * CCH * 5];
    __syncthreads();
    for (int i = tid; i < CCH * T1; i += blockDim.x) {
        int ci = i / T1;
        float v = g_buf1[b * CCH * T1 + i];
        xs[i] = fmaxf(fmaf(v, bsc[ci], bsh[ci]), 0.f);
    }
    __syncthreads();

    for (int c = 0; c < CCH; c++) {
        float s = 0.f, q = 0.f;
        for (int t = tid; t < T2; t += blockDim.x) {
            float a = bs[c];
            #pragma unroll
            for (int ci = 0; ci < CCH; ci++) {
                const float* xp = xs + ci * T1 + t;
                const float* wp = ws + (c * CCH + ci) * 5;
                #pragma unroll
                for (int k = 0; k < 5; k++) a = fmaf(xp[k], wp[k], a);
            }
            g_buf2[(b * CCH + c) * T2 + t] = a;
            s += a; q += a * a;
        }
        #pragma unroll
        for (int off = 16; off > 0; off >>= 1) {
            s += __shfl_down_sync(0xffffffffu, s, off);
            q += __shfl_down_sync(0xffffffffu, q, off);
        }
        if ((tid & 31) == 0) { sw[c][wid] = s; qw[c][wid] = q; }
    }
    __syncthreads();
    if (tid < CCH) {
        float s = 0.f, q = 0.f;
        #pragma unroll
        for (int wq = 0; wq < 8; wq++) { s += sw[tid][wq]; q += qw[tid][wq]; }
        atomicAdd(&g_s2[tid], (double)s);
        atomicAdd(&g_q2[tid], (double)q);
    }
}

// ---------------- K5: BN2+relu -> attn -> seq (bnfin folded in) ----------------
__global__ void k_attn(const float* __restrict__ aw,
                       const float* __restrict__ ab,
                       const float* __restrict__ bn2g,
                       const float* __restrict__ bn2b) {
    int b = blockIdx.x;
    int tid = threadIdx.x;
    __shared__ float xs[CCH * T2];
    __shared__ float ws[HID * CCH];
    __shared__ float bs[HID];
    __shared__ float bsc[CCH], bsh[CCH];
    if (tid < CCH)
        bn_coeff(g_s2, g_q2, (double)BATCH * T2, bn2g, bn2b, bsc, bsh, tid);
    if (tid >= 32 && tid < 32 + HID * CCH) ws[tid - 32] = aw[tid - 32];
    if (tid >= 128 && tid < 128 + HID) bs[tid - 128] = ab[tid - 128];
    __syncthreads();
    for (int i = tid; i < CCH * T2; i += blockDim.x) {
        int ci = i / T2;
        float v = g_buf2[b * CCH * T2 + i];
        xs[i] = fmaxf(fmaf(v, bsc[ci], bsh[ci]), 0.f);
    }
    __syncthreads();

    size_t base = ((size_t)(b >> 1)) * T2 * HID * 2 + (b & 1);
    for (int idx = tid; idx < T2 * HID; idx += blockDim.x) {
        int t = idx / HID, h = idx % HID;
        float a = bs[h];
        #pragma unroll
        for (int c = 0; c < CCH; c++) a = fmaf(xs[c * T2 + t], ws[h * CCH + c], a);
        g_seq[base + (size_t)idx * 2] = fmaxf(a, 0.f);
    }
}

// ---------------- K6: 120-layer LSTM (byte-identical to R10 champion) ----------------
__global__ void __launch_bounds__(NTH, 2)
k_lstm(const float* __restrict__ Wih, const float* __restrict__ Whh,
       const float* __restrict__ bih, const float* __restrict__ bhh) {
    extern __shared__ __align__(16) u64 smem[];
    u64* seq_s  = smem;                    // [T2*HID] packed (b0,b1)
    u64* hbuf   = smem + SEQ_U;            // [2][GL][HID]
    u64* bias_s = smem + SEQ_U + HBUF_U;   // [NTH][4]

    int pair = blockIdx.x;
    int b0 = pair * 2, b1 = b0 + 1;
    int tid = threadIdx.x;
    int j = tid / HID;   // local layer in group
    int i = tid % HID;   // hidden unit

    {
        const float4* src = (const float4*)(g_seq + (size_t)pair * T2 * HID * 2);
        float4* dst = (float4*)seq_s;
        for (int q = tid; q < (T2 * HID * 2) / 4; q += NTH) dst[q] = src[q];
    }

    for (int grp = 0; grp < NGRP; grp++) {
        int l = grp * GL + j;
        for (int q = tid; q < HBUF_U; q += NTH) hbuf[q] = 0ull;

        u64 wih2[4][HID], whh2[4][HID];
        {
            const float* Wi = Wih + (size_t)l * 48 * HID;
            const float* Wh = Whh + (size_t)l * 48 * HID;
            #pragma unroll
            for (int r = 0; r < 4; r++) {
                int row = r * HID + i;
                #pragma unroll
                for (int m = 0; m < HID; m++) {
                    float wi = Wi[row * HID + m];
                    float wh = Wh[row * HID + m];
                    wih2[r][m] = pack2(wi, wi);
                    whh2[r][m] = pack2(wh, wh);
                }
                float bb = bih[l * 48 + row] + bhh[l * 48 + row];
                bias_s[tid * 4 + r] = pack2(bb, bb);
            }
        }
        float c0 = 0.f, c1 = 0.f;
        __syncthreads();

        for (int k = 0; k < T2 + GL - 1; k++) {
            int t = k - j;
            if ((unsigned)t < (unsigned)T2) {
                int p = k & 1;
                const u64* xp = (j == 0) ? (seq_s + t * HID)
                                         : (hbuf + ((p ^ 1) * GL + (j - 1)) * HID);
                const u64* hp = hbuf + ((p ^ 1) * GL + j) * HID;

                u64 a0 = bias_s[tid * 4 + 0], a1 = bias_s[tid * 4 + 1];
                u64 a2 = bias_s[tid * 4 + 2], a3 = bias_s[tid * 4 + 3];

                u64 v[HID];
                #pragma unroll
                for (int q = 0; q < HID / 2; q++) {
                    ulonglong2 tv = ((const ulonglong2*)xp)[q];
                    v[2 * q] = tv.x; v[2 * q + 1] = tv.y;
                }
                #pragma unroll
                for (int m = 0; m < HID; m++) {
                    u64 xm = v[m];
                    a0 = ffma2(wih2[0][m], xm, a0);
                    a1 = ffma2(wih2[1][m], xm, a1);
                    a2 = ffma2(wih2[2][m], xm, a2);
                    a3 = ffma2(wih2[3][m], xm, a3);
                }
                #pragma unroll
                for (int q = 0; q < HID / 2; q++) {
                    ulonglong2 tv = ((const ulonglong2*)hp)[q];
                    v[2 * q] = tv.x; v[2 * q + 1] = tv.y;
                }
                #pragma unroll
                for (int m = 0; m < HID; m++) {
                    u64 hm = v[m];
                    a0 = ffma2(whh2[0][m], hm, a0);
                    a1 = ffma2(whh2[1][m], hm, a1);
                    a2 = ffma2(whh2[2][m], hm, a2);
                    a3 = ffma2(whh2[3][m], hm, a3);
                }
                float g0x, g0y, g1x, g1y, g2x, g2y, g3x, g3y;
                unpack2(a0, g0x, g0y);
                unpack2(a1, g1x, g1y);
                unpack2(a2, g2x, g2y);
                unpack2(a3, g3x, g3y);
                float gi = sigm_t(g0x), gf = sigm_t(g1x), gg = tanh_t(g2x), go = sigm_t(g3x);
                c0 = gf * c0 + gi * gg;
                float h0 = go * tanh_t(c0);
                gi = sigm_t(g0y); gf = sigm_t(g1y); gg = tanh_t(g2y); go = sigm_t(g3y);
                c1 = gf * c1 + gi * gg;
                float h1 = go * tanh_t(c1);

                u64 hpk = pack2(h0, h1);
                hbuf[(p * GL + j) * HID + i] = hpk;
                if (j == GL - 1) seq_s[t * HID + i] = hpk;
                if (t == T2 - 1) {
                    g_hid[((size_t)b0 * NLAY + l) * HID + i] = h0;
                    g_hid[((size_t)b1 * NLAY + l) * HID + i] = h1;
                }
            }
            __syncthreads();
        }
        __syncthreads();
    }
}

// ---------------- K7: MLP head -> (z, out, mu, log_var) ----------------
__global__ void k_head(const float* __restrict__ eps,
                       const float* __restrict__ l1w, const float* __restrict__ l1b,
                       const float* __restrict__ l2w, const float* __restrict__ l2b,
                       const float* __restrict__ muw, const float* __restrict__ mub,
                       const float* __restrict__ lvw, const float* __restrict__ lvb,
                       float* __restrict__ out) {
    __shared__ float W1[144], W2[144], WM[144], WV[144];
    __shared__ float B1[12], B2[12], BM[12], BV[12];
    int tid = threadIdx.x;
    for (int q = tid; q < 144; q += blockDim.x) {
        W1[q] = l1w[q]; W2[q] = l2w[q]; WM[q] = muw[q]; WV[q] = lvw[q];
    }
    if (tid < 12) { B1[tid] = l1b[tid]; B2[tid] = l2b[tid]; BM[tid] = mub[tid]; BV[tid] = lvb[tid]; }
    __syncthreads();

    int row = blockIdx.x * blockDim.x + tid;       // (b*120 + l)
    if (row >= BATCH * NLAY) return;
    const float* hp = g_hid + (size_t)row * HID;
    float h[HID], v1[HID], v2[HID];
    {
        float4 a = *(const float4*)(hp);
        float4 bq = *(const float4*)(hp + 4);
        float4 cq = *(const float4*)(hp + 8);
        h[0]=a.x; h[1]=a.y; h[2]=a.z; h[3]=a.w; h[4]=bq.x; h[5]=bq.y; h[6]=bq.z; h[7]=bq.w;
        h[8]=cq.x; h[9]=cq.y; h[10]=cq.z; h[11]=cq.w;
    }
    #pragma unroll
    for (int r = 0; r < HID; r++) {
        float a = B1[r];
        #pragma unroll
        for (int m = 0; m < HID; m++) a = fmaf(W1[r * HID + m], h[m], a);
        v1[r] = fmaxf(a, 0.f);
    }
    #pragma unroll
    for (int r = 0; r < HID; r++) {
        float a = B2[r];
        #pragma unroll
        for (int m = 0; m < HID; m++) a = fmaf(W2[r * HID + m], v1[m], a);
        v2[r] = fmaxf(a, 0.f);
    }
    #pragma unroll
    for (int r = 0; r < HID; r++) {
        float mu = BM[r], lv = BV[r];
        #pragma unroll
        for (int m = 0; m < HID; m++) {
            mu = fmaf(WM[r * HID + m], v2[m], mu);
            lv = fmaf(WV[r * HID + m], v2[m], lv);
        }
        float e = eps[(size_t)row * HID + r];
        float z = fmaf(__expf(0.5f * lv), e, mu);
        size_t idx = (size_t)row * HID + r;
        out[idx]              = z;
        out[NOUT + idx]       = v2[r];
        out[2 * (size_t)NOUT + idx] = mu;
        out[3 * (size_t)NOUT + idx] = lv;
    }
}

// ---------------- launcher ----------------
extern "C" void kernel_launch(void* const* d_in, const int* in_sizes, int n_in,
                              void* d_out, int out_size) {
    const float* x    = (const float*)d_in[0];
    const float* eps  = (const float*)d_in[1];
    const float* c1w  = (const float*)d_in[2];
    const float* c1b  = (const float*)d_in[3];
    const float* c2w  = (const float*)d_in[4];
    const float* c2b  = (const float*)d_in[5];
    const float* bn1g = (const float*)d_in[6];
    const float* bn1b = (const float*)d_in[7];
    const float* bn2g = (const float*)d_in[8];
    const float* bn2b = (const float*)d_in[9];
    const float* aw   = (const float*)d_in[10];
    const float* ab   = (const float*)d_in[11];
    const float* Wih  = (const float*)d_in[12];
    const float* Whh  = (const float*)d_in[13];
    const float* bih  = (const float*)d_in[14];
    const float* bhh  = (const float*)d_in[15];
    const float* l1w  = (const float*)d_in[16];
    const float* l1b  = (const float*)d_in[17];
    const float* l2w  = (const float*)d_in[18];
    const float* l2b  = (const float*)d_in[19];
    const float* muw  = (const float*)d_in[20];
    const float* mub  = (const float*)d_in[21];
    const float* lvw  = (const float*)d_in[22];
    const float* lvb  = (const float*)d_in[23];

    cudaFuncSetAttribute(k_lstm, cudaFuncAttributeMaxDynamicSharedMemorySize,
                         LSTM_SMEM_BYTES);

    k_zero<<<1, 32>>>();
    k_conv1<<<BATCH, 256>>>(x, c1w, c1b);
    k_conv2<<<BATCH, 256>>>(c2w, c2b, bn1g, bn1b);
    k_attn<<<BATCH, 256>>>(aw, ab, bn2g, bn2b);
    k_lstm<<<NPAIR, NTH, LSTM_SMEM_BYTES>>>(Wih, Whh, bih, bhh);
    k_head<<<(BATCH * NLAY) / 128, 128>>>(eps, l1w, l1b, l2w, l2b, muw, mub, lvw, lvb,
                                          (float*)d_out);
}

// round 17
// speedup vs baseline: 1.9653x; 1.0043x over previous
#include <cuda_runtime.h>
#include <math.h>

// ---------------- problem constants ----------------
#define BATCH 512
#define TIN   512
#define CCH   6
#define HID   12
#define NLAY  120
#define T1    508        // after conv1 (k=5 VALID)
#define T2    504        // after conv2
#define GL    10         // layers per pipeline group
#define NGRP  12         // 120 / 10
#define NTH   120        // GL * HID threads in LSTM block
#define NPAIR 256        // batch pairs (2 per block)
#define NOUT  (BATCH*NLAY*HID)   // 737280 per output tensor

typedef unsigned long long u64;

// dynamic smem for k_lstm (all u64):
#define SEQ_U   (T2*HID)
#define HBUF_U  (2*GL*HID)
#define BIAS_U  (NTH*4)
#define LSTM_SMEM_BYTES ((SEQ_U + HBUF_U + BIAS_U) * 8)

// ---------------- device scratch (static, no allocation) ----------------
__device__ double g_s1[CCH], g_q1[CCH], g_s2[CCH], g_q2[CCH];
__device__ float  g_buf1[BATCH*CCH*T1];
__device__ float  g_buf2[BATCH*CCH*T2];
__device__ float  g_seq [BATCH*T2*HID];   // pair-interleaved: [pair][t][h][lane2]
__device__ float  g_hid [BATCH*NLAY*HID];

// ---------------- f32x2 helpers (b64 operands -> "l" constraint) ----------------
__device__ __forceinline__ u64 ffma2(u64 a, u64 b, u64 c) {
    u64 d;
    asm("fma.rn.f32x2 %0, %1, %2, %3;" : "=l"(d) : "l"(a), "l"(b), "l"(c));
    return d;
}
__device__ __forceinline__ u64 pack2(float x, float y) {
    u64 d;
    asm("mov.b64 %0, {%1, %2};" : "=l"(d) : "f"(x), "f"(y));
    return d;
}
__device__ __forceinline__ void unpack2(u64 d, float& x, float& y) {
    asm("mov.b64 {%0, %1}, %2;" : "=f"(x), "=f"(y) : "l"(d));
}

// ---------------- activation helpers ----------------
__device__ __forceinline__ float tanh_t(float x) {
    float y;
    asm("tanh.approx.f32 %0, %1;" : "=f"(y) : "f"(x));
    return y;
}
__device__ __forceinline__ float sigm_t(float x) {
    return fmaf(0.5f, tanh_t(0.5f * x), 0.5f);
}

// BN scale/shift from raw stats (computed redundantly per block; 6 channels)
__device__ __forceinline__ void bn_coeff(const double* S, const double* Q, double n,
                                         const float* gam, const float* bet,
                                         float* sc_out, float* sh_out, int c) {
    double m = S[c] / n;
    double v = Q[c] / n - m * m;
    float sc = gam[c] * rsqrtf((float)v + 1e-5f);
    sc_out[c] = sc;
    sh_out[c] = bet[c] - (float)m * sc;
}

// ---------------- K0: zero BN stat accumulators ----------------
__global__ void k_zero() {
    int t = threadIdx.x;
    if (t < CCH) { g_s1[t] = 0.0; g_q1[t] = 0.0; g_s2[t] = 0.0; g_q2[t] = 0.0; }
}

// ---------------- K1: conv1 + BN1 stats (block-reduced atomics) ----------------
__global__ void k_conv1(const float* __restrict__ x,
                        const float* __restrict__ w,
                        const float* __restrict__ bias) {
    int b = blockIdx.x;
    int tid = threadIdx.x;
    int wid = tid >> 5;
    __shared__ float xs[CCH * TIN];
    __shared__ float ws[CCH * CCH * 5];
    __shared__ float bs[CCH];
    __shared__ float sw[CCH][8], qw[CCH][8];   // per-warp partials
    for (int i = tid; i < CCH * TIN; i += blockDim.x) xs[i] = x[b * CCH * TIN + i];
    if (tid < CCH * CCH * 5) ws[tid] = w[tid];
    if (tid < CCH) bs[tid] = bias[tid];
    __syncthreads();

    for (int c = 0; c < CCH; c++) {
        float s = 0.f, q = 0.f;
        for (int t = tid; t < T1; t += blockDim.x) {
            float a = bs[c];
            #pragma unroll
            for (int ci = 0; ci < CCH; ci++) {
                const float* xp = xs + ci * TIN + t;
                const float* wp = ws + (c * CCH + ci) * 5;
                #pragma unroll
                for (int k = 0; k < 5; k++) a = fmaf(xp[k], wp[k], a);
            }
            g_buf1[(b * CCH + c) * T1 + t] = a;
            s += a; q += a * a;
        }
        #pragma unroll
        for (int off = 16; off > 0; off >>= 1) {
            s += __shfl_down_sync(0xffffffffu, s, off);
            q += __shfl_down_sync(0xffffffffu, q, off);
        }
        if ((tid & 31) == 0) { sw[c][wid] = s; qw[c][wid] = q; }
    }
    __syncthreads();
    if (tid < CCH) {
        float s = 0.f, q = 0.f;
        #pragma unroll
        for (int wq = 0; wq < 8; wq++) { s += sw[tid][wq]; q += qw[tid][wq]; }
        atomicAdd(&g_s1[tid], (double)s);
        atomicAdd(&g_q1[tid], (double)q);
    }
}

// ---------------- K3: BN1+relu -> conv2 + BN2 stats (bnfin folded in) ----------------
__global__ void k_conv2(const float* __restrict__ w,
                        const float* __restrict__ bias,
                        const float* __restrict__ bn1g,
                        const float* __restrict__ bn1b) {
    int b = blockIdx.x;
    int tid = threadIdx.x;
    int wid = tid >> 5;
    __shared__ float xs[CCH * T1];
    __shared__ float ws[CCH * CCH * 5];
    __shared__ float bs[CCH];
    __shared__ float bsc[CCH], bsh[CCH];
    __shared__ float sw[CCH][8], qw[CCH][8];
    if (tid < CCH)
        bn_coeff(g_s1, g_q1, (double)BATCH * T1, bn1g, bn1b, bsc, bsh, tid);
    if (tid < CCH * CCH * 5) ws[tid] = w[tid];
    if (tid >= CCH * CCH * 5 && tid < CCH * CCH * 5 + CCH)
        bs[tid - CCH * CCH * 5] = bias[tid - CCH * CCH * 5];
    __syncthreads();
    for (int i = tid; i < CCH * T1; i += blockDim.x) {
        int ci = i / T1;
        float v = g_buf1[b * CCH * T1 + i];
        xs[i] = fmaxf(fmaf(v, bsc[ci], bsh[ci]), 0.f);
    }
    __syncthreads();

    for (int c = 0; c < CCH; c++) {
        float s = 0.f, q = 0.f;
        for (int t = tid; t < T2; t += blockDim.x) {
            float a = bs[c];
            #pragma unroll
            for (int ci = 0; ci < CCH; ci++) {
                const float* xp = xs + ci * T1 + t;
                const float* wp = ws + (c * CCH + ci) * 5;
                #pragma unroll
                for (int k = 0; k < 5; k++) a = fmaf(xp[k], wp[k], a);
            }
            g_buf2[(b * CCH + c) * T2 + t] = a;
            s += a; q += a * a;
        }
        #pragma unroll
        for (int off = 16; off > 0; off >>= 1) {
            s += __shfl_down_sync(0xffffffffu, s, off);
            q += __shfl_down_sync(0xffffffffu, q, off);
        }
        if ((tid & 31) == 0) { sw[c][wid] = s; qw[c][wid] = q; }
    }
    __syncthreads();
    if (tid < CCH) {
        float s = 0.f, q = 0.f;
        #pragma unroll
        for (int wq = 0; wq < 8; wq++) { s += sw[tid][wq]; q += qw[tid][wq]; }
        atomicAdd(&g_s2[tid], (double)s);
        atomicAdd(&g_q2[tid], (double)q);
    }
}

// ---------------- K5: BN2+relu -> attn -> seq (bnfin folded in) ----------------
__global__ void k_attn(const float* __restrict__ aw,
                       const float* __restrict__ ab,
                       const float* __restrict__ bn2g,
                       const float* __restrict__ bn2b) {
    int b = blockIdx.x;
    int tid = threadIdx.x;
    __shared__ float xs[CCH * T2];
    __shared__ float ws[HID * CCH];
    __shared__ float bs[HID];
    __shared__ float bsc[CCH], bsh[CCH];
    if (tid < CCH)
        bn_coeff(g_s2, g_q2, (double)BATCH * T2, bn2g, bn2b, bsc, bsh, tid);
    if (tid >= 32 && tid < 32 + HID * CCH) ws[tid - 32] = aw[tid - 32];
    if (tid >= 128 && tid < 128 + HID) bs[tid - 128] = ab[tid - 128];
    __syncthreads();
    for (int i = tid; i < CCH * T2; i += blockDim.x) {
        int ci = i / T2;
        float v = g_buf2[b * CCH * T2 + i];
        xs[i] = fmaxf(fmaf(v, bsc[ci], bsh[ci]), 0.f);
    }
    __syncthreads();

    size_t base = ((size_t)(b >> 1)) * T2 * HID * 2 + (b & 1);
    for (int idx = tid; idx < T2 * HID; idx += blockDim.x) {
        int t = idx / HID, h = idx % HID;
        float a = bs[h];
        #pragma unroll
        for (int c = 0; c < CCH; c++) a = fmaf(xs[c * T2 + t], ws[h * CCH + c], a);
        g_seq[base + (size_t)idx * 2] = fmaxf(a, 0.f);
    }
}

// ---------------- K6: 120-layer LSTM (byte-identical to R10 champion) ----------------
__global__ void __launch_bounds__(NTH, 2)
k_lstm(const float* __restrict__ Wih, const float* __restrict__ Whh,
       const float* __restrict__ bih, const float* __restrict__ bhh) {
    extern __shared__ __align__(16) u64 smem[];
    u64* seq_s  = smem;                    // [T2*HID] packed (b0,b1)
    u64* hbuf   = smem + SEQ_U;            // [2][GL][HID]
    u64* bias_s = smem + SEQ_U + HBUF_U;   // [NTH][4]

    int pair = blockIdx.x;
    int b0 = pair * 2, b1 = b0 + 1;
    int tid = threadIdx.x;
    int j = tid / HID;   // local layer in group
    int i = tid % HID;   // hidden unit

    {
        const float4* src = (const float4*)(g_seq + (size_t)pair * T2 * HID * 2);
        float4* dst = (float4*)seq_s;
        for (int q = tid; q < (T2 * HID * 2) / 4; q += NTH) dst[q] = src[q];
    }

    for (int grp = 0; grp < NGRP; grp++) {
        int l = grp * GL + j;
        for (int q = tid; q < HBUF_U; q += NTH) hbuf[q] = 0ull;

        u64 wih2[4][HID], whh2[4][HID];
        {
            const float* Wi = Wih + (size_t)l * 48 * HID;
            const float* Wh = Whh + (size_t)l * 48 * HID;
            #pragma unroll
            for (int r = 0; r < 4; r++) {
                int row = r * HID + i;
                #pragma unroll
                for (int m = 0; m < HID; m++) {
                    float wi = Wi[row * HID + m];
                    float wh = Wh[row * HID + m];
                    wih2[r][m] = pack2(wi, wi);
                    whh2[r][m] = pack2(wh, wh);
                }
                float bb = bih[l * 48 + row] + bhh[l * 48 + row];
                bias_s[tid * 4 + r] = pack2(bb, bb);
            }
        }
        float c0 = 0.f, c1 = 0.f;
        __syncthreads();

        for (int k = 0; k < T2 + GL - 1; k++) {
            int t = k - j;
            if ((unsigned)t < (unsigned)T2) {
                int p = k & 1;
                const u64* xp = (j == 0) ? (seq_s + t * HID)
                                         : (hbuf + ((p ^ 1) * GL + (j - 1)) * HID);
                const u64* hp = hbuf + ((p ^ 1) * GL + j) * HID;

                u64 a0 = bias_s[tid * 4 + 0], a1 = bias_s[tid * 4 + 1];
                u64 a2 = bias_s[tid * 4 + 2], a3 = bias_s[tid * 4 + 3];

                u64 v[HID];
                #pragma unroll
                for (int q = 0; q < HID / 2; q++) {
                    ulonglong2 tv = ((const ulonglong2*)xp)[q];
                    v[2 * q] = tv.x; v[2 * q + 1] = tv.y;
                }
                #pragma unroll
                for (int m = 0; m < HID; m++) {
                    u64 xm = v[m];
                    a0 = ffma2(wih2[0][m], xm, a0);
                    a1 = ffma2(wih2[1][m], xm, a1);
                    a2 = ffma2(wih2[2][m], xm, a2);
                    a3 = ffma2(wih2[3][m], xm, a3);
                }
                #pragma unroll
                for (int q = 0; q < HID / 2; q++) {
                    ulonglong2 tv = ((const ulonglong2*)hp)[q];
                    v[2 * q] = tv.x; v[2 * q + 1] = tv.y;
                }
                #pragma unroll
                for (int m = 0; m < HID; m++) {
                    u64 hm = v[m];
                    a0 = ffma2(whh2[0][m], hm, a0);
                    a1 = ffma2(whh2[1][m], hm, a1);
                    a2 = ffma2(whh2[2][m], hm, a2);
                    a3 = ffma2(whh2[3][m], hm, a3);
                }
                float g0x, g0y, g1x, g1y, g2x, g2y, g3x, g3y;
                unpack2(a0, g0x, g0y);
                unpack2(a1, g1x, g1y);
                unpack2(a2, g2x, g2y);
                unpack2(a3, g3x, g3y);
                float gi = sigm_t(g0x), gf = sigm_t(g1x), gg = tanh_t(g2x), go = sigm_t(g3x);
                c0 = gf * c0 + gi * gg;
                float h0 = go * tanh_t(c0);
                gi = sigm_t(g0y); gf = sigm_t(g1y); gg = tanh_t(g2y); go = sigm_t(g3y);
                c1 = gf * c1 + gi * gg;
                float h1 = go * tanh_t(c1);

                u64 hpk = pack2(h0, h1);
                hbuf[(p * GL + j) * HID + i] = hpk;
                if (j == GL - 1) seq_s[t * HID + i] = hpk;
                if (t == T2 - 1) {
                    g_hid[((size_t)b0 * NLAY + l) * HID + i] = h0;
                    g_hid[((size_t)b1 * NLAY + l) * HID + i] = h1;
                }
            }
            __syncthreads();
        }
        __syncthreads();
    }
}

// ---------------- K7: MLP head -> (z, out, mu, log_var), vectorized I/O ----------------
__global__ void k_head(const float* __restrict__ eps,
                       const float* __restrict__ l1w, const float* __restrict__ l1b,
                       const float* __restrict__ l2w, const float* __restrict__ l2b,
                       const float* __restrict__ muw, const float* __restrict__ mub,
                       const float* __restrict__ lvw, const float* __restrict__ lvb,
                       float* __restrict__ out) {
    __shared__ float W1[144], W2[144], WM[144], WV[144];
    __shared__ float B1[12], B2[12], BM[12], BV[12];
    int tid = threadIdx.x;
    for (int q = tid; q < 144; q += blockDim.x) {
        W1[q] = l1w[q]; W2[q] = l2w[q]; WM[q] = muw[q]; WV[q] = lvw[q];
    }
    if (tid < 12) { B1[tid] = l1b[tid]; B2[tid] = l2b[tid]; BM[tid] = mub[tid]; BV[tid] = lvb[tid]; }
    __syncthreads();

    int row = blockIdx.x * blockDim.x + tid;       // (b*120 + l)
    if (row >= BATCH * NLAY) return;
    const float* hp = g_hid + (size_t)row * HID;
    float h[HID], v1[HID], v2[HID], mu[HID], lv[HID], z[HID];
    {
        float4 a = *(const float4*)(hp);
        float4 bq = *(const float4*)(hp + 4);
        float4 cq = *(const float4*)(hp + 8);
        h[0]=a.x; h[1]=a.y; h[2]=a.z; h[3]=a.w; h[4]=bq.x; h[5]=bq.y; h[6]=bq.z; h[7]=bq.w;
        h[8]=cq.x; h[9]=cq.y; h[10]=cq.z; h[11]=cq.w;
    }
    float e[HID];
    {
        const float4* ep = (const float4*)(eps + (size_t)row * HID);
        float4 a = ep[0], bq = ep[1], cq = ep[2];
        e[0]=a.x; e[1]=a.y; e[2]=a.z; e[3]=a.w; e[4]=bq.x; e[5]=bq.y; e[6]=bq.z; e[7]=bq.w;
        e[8]=cq.x; e[9]=cq.y; e[10]=cq.z; e[11]=cq.w;
    }
    #pragma unroll
    for (int r = 0; r < HID; r++) {
        float a = B1[r];
        #pragma unroll
        for (int m = 0; m < HID; m++) a = fmaf(W1[r * HID + m], h[m], a);
        v1[r] = fmaxf(a, 0.f);
    }
    #pragma unroll
    for (int r = 0; r < HID; r++) {
        float a = B2[r];
        #pragma unroll
        for (int m = 0; m < HID; m++) a = fmaf(W2[r * HID + m], v1[m], a);
        v2[r] = fmaxf(a, 0.f);
    }
    #pragma unroll
    for (int r = 0; r < HID; r++) {
        float m1 = BM[r], m2 = BV[r];
        #pragma unroll
        for (int m = 0; m < HID; m++) {
            m1 = fmaf(WM[r * HID + m], v2[m], m1);
            m2 = fmaf(WV[r * HID + m], v2[m], m2);
        }
        mu[r] = m1; lv[r] = m2;
        z[r] = fmaf(__expf(0.5f * m2), e[r], m1);
    }
    // vectorized stores: 3 float4 per output tensor
    size_t base = (size_t)row * HID;
    float4* oz = (float4*)(out + base);
    float4* oo = (float4*)(out + NOUT + base);
    float4* om = (float4*)(out + 2 * (size_t)NOUT + base);
    float4* ol = (float4*)(out + 3 * (size_t)NOUT + base);
    #pragma unroll
    for (int q = 0; q < 3; q++) {
        oz[q] = make_float4(z[4*q],  z[4*q+1],  z[4*q+2],  z[4*q+3]);
        oo[q] = make_float4(v2[4*q], v2[4*q+1], v2[4*q+2], v2[4*q+3]);
        om[q] = make_float4(mu[4*q], mu[4*q+1], mu[4*q+2], mu[4*q+3]);
        ol[q] = make_float4(lv[4*q], lv[4*q+1], lv[4*q+2], lv[4*q+3]);
    }
}

// ---------------- launcher ----------------
extern "C" void kernel_launch(void* const* d_in, const int* in_sizes, int n_in,
                              void* d_out, int out_size) {
    const float* x    = (const float*)d_in[0];
    const float* eps  = (const float*)d_in[1];
    const float* c1w  = (const float*)d_in[2];
    const float* c1b  = (const float*)d_in[3];
    const float* c2w  = (const float*)d_in[4];
    const float* c2b  = (const float*)d_in[5];
    const float* bn1g = (const float*)d_in[6];
    const float* bn1b = (const float*)d_in[7];
    const float* bn2g = (const float*)d_in[8];
    const float* bn2b = (const float*)d_in[9];
    const float* aw   = (const float*)d_in[10];
    const float* ab   = (const float*)d_in[11];
    const float* Wih  = (const float*)d_in[12];
    const float* Whh  = (const float*)d_in[13];
    const float* bih  = (const float*)d_in[14];
    const float* bhh  = (const float*)d_in[15];
    const float* l1w  = (const float*)d_in[16];
    const float* l1b  = (const float*)d_in[17];
    const float* l2w  = (const float*)d_in[18];
    const float* l2b  = (const float*)d_in[19];
    const float* muw  = (const float*)d_in[20];
    const float* mub  = (const float*)d_in[21];
    const float* lvw  = (const float*)d_in[22];
    const float* lvb  = (const float*)d_in[23];

    cudaFuncSetAttribute(k_lstm, cudaFuncAttributeMaxDynamicSharedMemorySize,
                         LSTM_SMEM_BYTES);

    k_zero<<<1, 32>>>();
    k_conv1<<<BATCH, 256>>>(x, c1w, c1b);
    k_conv2<<<BATCH, 256>>>(c2w, c2b, bn1g, bn1b);
    k_attn<<<BATCH, 256>>>(aw, ab, bn2g, bn2b);
    k_lstm<<<NPAIR, NTH, LSTM_SMEM_BYTES>>>(Wih, Whh, bih, bhh);
    k_head<<<(BATCH * NLAY) / 128, 128>>>(eps, l1w, l1b, l2w, l2b, muw, mub, lvw, lvb,
                                          (float*)d_out);
}